// round 1
// baseline (speedup 1.0000x reference)
#include <cuda_runtime.h>
#include <cstdint>

#define LN_EPS 1e-5f

static constexpr int Fdim = 64;
static constexpr int Hdim = 128;

// Round-to-nearest tf32 (kept in fp32 container, low mantissa bits zeroed)
__device__ __forceinline__ float tf32_rna(float x) {
    uint32_t r;
    asm("cvt.rna.tf32.f32 %0, %1;" : "=r"(r) : "f"(x));
    return __uint_as_float(r);
}

__device__ __forceinline__ void mma_tf32(float c[4], const uint32_t a[4], const uint32_t b[2]) {
    asm volatile(
        "mma.sync.aligned.m16n8k8.row.col.f32.tf32.tf32.f32 "
        "{%0,%1,%2,%3}, {%4,%5,%6,%7}, {%8,%9}, {%0,%1,%2,%3};\n"
        : "+f"(c[0]), "+f"(c[1]), "+f"(c[2]), "+f"(c[3])
        : "r"(a[0]), "r"(a[1]), "r"(a[2]), "r"(a[3]), "r"(b[0]), "r"(b[1]));
}

// Phase 1: per 16-row warp tile: tf32 3-split GEMM (x@W^T + b) -> LayerNorm -> ReLU
//          -> write y to out[:, :, 0:H] -> masked max-pool via atomicMax into g.
extern "C" __global__ void __launch_bounds__(256)
phase1_kernel(const float* __restrict__ x, const int* __restrict__ mask,
              const float* __restrict__ W, const float* __restrict__ bias,
              const float* __restrict__ gamma, const float* __restrict__ beta,
              float* __restrict__ out, int* __restrict__ gI, int L)
{
    extern __shared__ float4 Bfrag[];   // [8 ksteps][16 ntiles][32 lanes] = 64 KB
    const int tid = threadIdx.x;

    // Pre-pack W into mma B-fragment order: per lane {b0_hi, b1_hi, b0_lo, b1_lo}
    for (int idx = tid; idx < 8 * 16 * 32; idx += 256) {
        int lane = idx & 31;
        int t    = (idx >> 5) & 15;
        int ks   = idx >> 9;
        int q = lane >> 2, s = lane & 3;
        int h  = t * 8 + q;
        int f0 = ks * 8 + s;
        float w0 = W[h * Fdim + f0];
        float w1 = W[h * Fdim + f0 + 4];
        float w0h = tf32_rna(w0), w1h = tf32_rna(w1);
        Bfrag[idx] = make_float4(w0h, w1h, tf32_rna(w0 - w0h), tf32_rna(w1 - w1h));
    }
    __syncthreads();

    const int lane = tid & 31;
    const int warp = tid >> 5;
    const int q = lane >> 2, s = lane & 3;
    const int row_base = blockIdx.x * 128 + warp * 16;   // 16 rows per warp, same n

    float acc[16][4];
    #pragma unroll
    for (int t = 0; t < 16; t++) {
        acc[t][0] = acc[t][1] = acc[t][2] = acc[t][3] = 0.f;
    }

    const float* xA = x + (size_t)(row_base + q) * Fdim;
    #pragma unroll
    for (int ks = 0; ks < 8; ks++) {
        const int c0 = ks * 8 + s;
        float a0 = xA[c0];
        float a1 = xA[8 * Fdim + c0];
        float a2 = xA[c0 + 4];
        float a3 = xA[8 * Fdim + c0 + 4];
        float h0 = tf32_rna(a0), h1 = tf32_rna(a1), h2 = tf32_rna(a2), h3 = tf32_rna(a3);
        uint32_t ah[4] = {__float_as_uint(h0), __float_as_uint(h1),
                          __float_as_uint(h2), __float_as_uint(h3)};
        uint32_t al[4] = {__float_as_uint(tf32_rna(a0 - h0)), __float_as_uint(tf32_rna(a1 - h1)),
                          __float_as_uint(tf32_rna(a2 - h2)), __float_as_uint(tf32_rna(a3 - h3))};
        const float4* Bp = Bfrag + ks * 512 + lane;
        #pragma unroll
        for (int t = 0; t < 16; t++) {
            float4 bv = Bp[t * 32];
            uint32_t bh[2] = {__float_as_uint(bv.x), __float_as_uint(bv.y)};
            uint32_t bl[2] = {__float_as_uint(bv.z), __float_as_uint(bv.w)};
            mma_tf32(acc[t], ah, bh);   // hi*hi
            mma_tf32(acc[t], al, bh);   // lo*hi
            mma_tf32(acc[t], ah, bl);   // hi*lo
        }
    }

    // bias before LN stats
    #pragma unroll
    for (int t = 0; t < 16; t++) {
        float2 bb = *reinterpret_cast<const float2*>(bias + t * 8 + 2 * s);
        acc[t][0] += bb.x; acc[t][1] += bb.y;
        acc[t][2] += bb.x; acc[t][3] += bb.y;
    }

    // LayerNorm stats: row q (c0,c1) and row q+8 (c2,c3), reduced across the 4-lane quad
    float sumA = 0.f, sqA = 0.f, sumB = 0.f, sqB = 0.f;
    #pragma unroll
    for (int t = 0; t < 16; t++) {
        sumA += acc[t][0] + acc[t][1];
        sqA  += acc[t][0] * acc[t][0] + acc[t][1] * acc[t][1];
        sumB += acc[t][2] + acc[t][3];
        sqB  += acc[t][2] * acc[t][2] + acc[t][3] * acc[t][3];
    }
    #pragma unroll
    for (int m = 1; m <= 2; m <<= 1) {
        sumA += __shfl_xor_sync(0xffffffffu, sumA, m);
        sqA  += __shfl_xor_sync(0xffffffffu, sqA, m);
        sumB += __shfl_xor_sync(0xffffffffu, sumB, m);
        sqB  += __shfl_xor_sync(0xffffffffu, sqB, m);
    }
    const float inv = 1.0f / (float)Hdim;
    float muA = sumA * inv, muB = sumB * inv;
    float varA = fmaxf(sqA * inv - muA * muA, 0.f);
    float varB = fmaxf(sqB * inv - muB * muB, 0.f);
    float rsA = rsqrtf(varA + LN_EPS);
    float rsB = rsqrtf(varB + LN_EPS);

    const int rowA = row_base + q;
    const int rowB = rowA + 8;
    const bool mA = (mask[rowA] != 0);
    const bool mB = (mask[rowB] != 0);
    float* outA = out + (size_t)rowA * (2 * Hdim);
    float* outB = out + (size_t)rowB * (2 * Hdim);

    float p0[16], p1[16];
    #pragma unroll
    for (int t = 0; t < 16; t++) {
        int col = t * 8 + 2 * s;
        float2 gg = *reinterpret_cast<const float2*>(gamma + col);
        float2 bt = *reinterpret_cast<const float2*>(beta + col);
        float yA0 = fmaxf((acc[t][0] - muA) * rsA * gg.x + bt.x, 0.f);
        float yA1 = fmaxf((acc[t][1] - muA) * rsA * gg.y + bt.y, 0.f);
        float yB0 = fmaxf((acc[t][2] - muB) * rsB * gg.x + bt.x, 0.f);
        float yB1 = fmaxf((acc[t][3] - muB) * rsB * gg.y + bt.y, 0.f);
        *reinterpret_cast<float2*>(outA + col) = make_float2(yA0, yA1);
        *reinterpret_cast<float2*>(outB + col) = make_float2(yB0, yB1);
        p0[t] = fmaxf(mA ? yA0 : 0.f, mB ? yB0 : 0.f);
        p1[t] = fmaxf(mA ? yA1 : 0.f, mB ? yB1 : 0.f);
    }

    // reduce pooled max over the 8 q-groups (lane bits 2..4)
    #pragma unroll
    for (int t = 0; t < 16; t++) {
        #pragma unroll
        for (int m = 4; m <= 16; m <<= 1) {
            p0[t] = fmaxf(p0[t], __shfl_xor_sync(0xffffffffu, p0[t], m));
            p1[t] = fmaxf(p1[t], __shfl_xor_sync(0xffffffffu, p1[t], m));
        }
    }
    if (q == 0) {
        const int n = row_base / L;
        int* gbase = gI + n * Hdim;
        #pragma unroll
        for (int t = 0; t < 16; t++) {
            int col = t * 8 + 2 * s;
            // values are ReLU'd (>= 0) and g initialized to 0, so int-compare == float-compare
            atomicMax(gbase + col,     __float_as_int(p0[t]));
            atomicMax(gbase + col + 1, __float_as_int(p1[t]));
        }
    }
}

// Phase 2: broadcast g[n, :] into out[n, l, H:2H] for every l
extern "C" __global__ void __launch_bounds__(256)
phase2_kernel(const float4* __restrict__ g4, float* __restrict__ out, int L)
{
    int idx = blockIdx.x * blockDim.x + threadIdx.x;   // N*L*32 threads
    int h4  = idx & 31;
    int row = idx >> 5;                 // global row = n*L + l
    int n   = row / L;
    float4 v = g4[n * 32 + h4];
    reinterpret_cast<float4*>(out + (size_t)row * (2 * Hdim) + Hdim)[h4] = v;
}

extern "C" void kernel_launch(void* const* d_in, const int* in_sizes, int n_in,
                              void* d_out, int out_size) {
    const float* x     = (const float*)d_in[0];
    const int*   mask  = (const int*)d_in[1];
    const float* W     = (const float*)d_in[2];
    const float* bias  = (const float*)d_in[3];
    const float* gamma = (const float*)d_in[4];
    const float* beta  = (const float*)d_in[5];
    float* out = (float*)d_out;

    const int NL = in_sizes[1];                          // N*L (mask element count)
    const long long ysize = (long long)NL * 2 * Hdim;    // out[N,L,2H] elements
    const int N = (int)(((long long)out_size - ysize) / Hdim);
    const int L = NL / N;
    float* g = out + ysize;                              // g[N,H] lives at the tail

    cudaFuncSetAttribute(phase1_kernel, cudaFuncAttributeMaxDynamicSharedMemorySize, 65536);

    // init pooled max to 0 (valid identity: pooled values are post-ReLU >= 0)
    cudaMemsetAsync(g, 0, (size_t)N * Hdim * sizeof(float), 0);

    phase1_kernel<<<NL / 128, 256, 65536>>>(x, mask, W, bias, gamma, beta, out, (int*)g, L);

    const int total = NL * (Hdim / 4);
    phase2_kernel<<<total / 256, 256>>>((const float4*)g, out, L);
}

// round 2
// speedup vs baseline: 1.0704x; 1.0704x over previous
#include <cuda_runtime.h>
#include <cuda_bf16.h>
#include <cstdint>

#define LN_EPS 1e-5f

static constexpr int Fdim = 64;
static constexpr int Hdim = 128;

// bf16 round-trip (value of the bf16 rounding, in fp32)
__device__ __forceinline__ float bf16_round(float x) {
    return __bfloat162float(__float2bfloat16_rn(x));
}
// pack two floats as bf16x2: lo -> low half, hi -> high half
__device__ __forceinline__ uint32_t packbf(float lo, float hi) {
    uint32_t r;
    asm("cvt.rn.bf16x2.f32 %0, %1, %2;" : "=r"(r) : "f"(hi), "f"(lo));
    return r;
}

__device__ __forceinline__ void mma_bf16(float c[4], const uint32_t a[4], const uint32_t b[2]) {
    asm volatile(
        "mma.sync.aligned.m16n8k16.row.col.f32.bf16.bf16.f32 "
        "{%0,%1,%2,%3}, {%4,%5,%6,%7}, {%8,%9}, {%0,%1,%2,%3};\n"
        : "+f"(c[0]), "+f"(c[1]), "+f"(c[2]), "+f"(c[3])
        : "r"(a[0]), "r"(a[1]), "r"(a[2]), "r"(a[3]), "r"(b[0]), "r"(b[1]));
}

// One CTA per batch n. 8 warps x 16 rows = 128 rows per sweep, L/128 sweeps.
// GEMM (bf16x3 split) -> bias -> LayerNorm -> ReLU -> write y -> in-block masked
// max-pool -> write g and broadcast g into out[:, :, H:2H]. No atomics, no 2nd pass.
extern "C" __global__ void __launch_bounds__(256)
fused_kernel(const float* __restrict__ x, const int* __restrict__ mask,
             const float* __restrict__ W, const float* __restrict__ bias,
             const float* __restrict__ gamma, const float* __restrict__ beta,
             float* __restrict__ out, float* __restrict__ gout, int L)
{
    __shared__ uint4  Bfrag[4 * 16 * 32];   // [kstep][ntile][lane] {bh0,bh1,bl0,bl1} = 32 KB
    __shared__ float  sPool[8 * 128];       // per-warp pooled max
    __shared__ float  gsm[128];             // final pooled vector

    const int tid = threadIdx.x;
    const int n   = blockIdx.x;

    // ---- pack W into bf16 mma B-fragment order (hi + residual lo) ----
    for (int idx = tid; idx < 4 * 16 * 32; idx += 256) {
        int lane = idx & 31;
        int t    = (idx >> 5) & 15;
        int ks   = idx >> 9;
        int q = lane >> 2, s = lane & 3;
        int h  = t * 8 + q;
        int f0 = ks * 16 + s * 2;
        float2 w01 = *reinterpret_cast<const float2*>(W + h * Fdim + f0);
        float2 w89 = *reinterpret_cast<const float2*>(W + h * Fdim + f0 + 8);
        uint4 v;
        v.x = packbf(w01.x, w01.y);                                  // hi, k0..k1
        v.y = packbf(w89.x, w89.y);                                  // hi, k8..k9
        v.z = packbf(w01.x - bf16_round(w01.x), w01.y - bf16_round(w01.y));  // lo
        v.w = packbf(w89.x - bf16_round(w89.x), w89.y - bf16_round(w89.y));
        Bfrag[idx] = v;
    }
    __syncthreads();

    const int lane = tid & 31;
    const int warp = tid >> 5;
    const int q = lane >> 2, s = lane & 3;

    float pool0[16], pool1[16];
    #pragma unroll
    for (int t = 0; t < 16; t++) { pool0[t] = 0.f; pool1[t] = 0.f; }

    for (int rb = warp * 16; rb < L; rb += 128) {
        const size_t rowA = (size_t)n * L + rb + q;
        const size_t rowB = rowA + 8;
        const float* xA = x + rowA * Fdim;
        const float* xB = x + rowB * Fdim;

        float acc[16][4];
        #pragma unroll
        for (int t = 0; t < 16; t++)
            acc[t][0] = acc[t][1] = acc[t][2] = acc[t][3] = 0.f;

        #pragma unroll
        for (int ks = 0; ks < 4; ks++) {
            const int f0 = ks * 16 + s * 2;
            float2 A0 = *reinterpret_cast<const float2*>(xA + f0);
            float2 A8 = *reinterpret_cast<const float2*>(xA + f0 + 8);
            float2 B0 = *reinterpret_cast<const float2*>(xB + f0);
            float2 B8 = *reinterpret_cast<const float2*>(xB + f0 + 8);
            uint32_t ah[4] = { packbf(A0.x, A0.y), packbf(B0.x, B0.y),
                               packbf(A8.x, A8.y), packbf(B8.x, B8.y) };
            uint32_t al[4] = {
                packbf(A0.x - bf16_round(A0.x), A0.y - bf16_round(A0.y)),
                packbf(B0.x - bf16_round(B0.x), B0.y - bf16_round(B0.y)),
                packbf(A8.x - bf16_round(A8.x), A8.y - bf16_round(A8.y)),
                packbf(B8.x - bf16_round(B8.x), B8.y - bf16_round(B8.y)) };
            const uint4* Bp = Bfrag + ks * 512 + lane;
            #pragma unroll
            for (int t = 0; t < 16; t++) {
                uint4 bv = Bp[t * 32];
                uint32_t bh[2] = { bv.x, bv.y };
                uint32_t bl[2] = { bv.z, bv.w };
                mma_bf16(acc[t], ah, bh);   // hi*hi
                mma_bf16(acc[t], al, bh);   // lo*hi
                mma_bf16(acc[t], ah, bl);   // hi*lo
            }
        }

        // bias before LN stats
        #pragma unroll
        for (int t = 0; t < 16; t++) {
            float2 bb = *reinterpret_cast<const float2*>(bias + t * 8 + 2 * s);
            acc[t][0] += bb.x; acc[t][1] += bb.y;
            acc[t][2] += bb.x; acc[t][3] += bb.y;
        }

        // LayerNorm stats across the 4-lane quad (rows q and q+8)
        float sumA = 0.f, sqA = 0.f, sumB = 0.f, sqB = 0.f;
        #pragma unroll
        for (int t = 0; t < 16; t++) {
            sumA += acc[t][0] + acc[t][1];
            sqA  += acc[t][0] * acc[t][0] + acc[t][1] * acc[t][1];
            sumB += acc[t][2] + acc[t][3];
            sqB  += acc[t][2] * acc[t][2] + acc[t][3] * acc[t][3];
        }
        #pragma unroll
        for (int m = 1; m <= 2; m <<= 1) {
            sumA += __shfl_xor_sync(0xffffffffu, sumA, m);
            sqA  += __shfl_xor_sync(0xffffffffu, sqA, m);
            sumB += __shfl_xor_sync(0xffffffffu, sumB, m);
            sqB  += __shfl_xor_sync(0xffffffffu, sqB, m);
        }
        const float inv = 1.0f / (float)Hdim;
        float muA = sumA * inv, muB = sumB * inv;
        float varA = fmaxf(sqA * inv - muA * muA, 0.f);
        float varB = fmaxf(sqB * inv - muB * muB, 0.f);
        float rsA = rsqrtf(varA + LN_EPS);
        float rsB = rsqrtf(varB + LN_EPS);

        const bool mA = (mask[rowA] != 0);
        const bool mB = (mask[rowB] != 0);
        float* outA = out + rowA * (2 * Hdim);
        float* outB = out + rowB * (2 * Hdim);

        #pragma unroll
        for (int t = 0; t < 16; t++) {
            int col = t * 8 + 2 * s;
            float2 gg = *reinterpret_cast<const float2*>(gamma + col);
            float2 bt = *reinterpret_cast<const float2*>(beta + col);
            float yA0 = fmaxf((acc[t][0] - muA) * rsA * gg.x + bt.x, 0.f);
            float yA1 = fmaxf((acc[t][1] - muA) * rsA * gg.y + bt.y, 0.f);
            float yB0 = fmaxf((acc[t][2] - muB) * rsB * gg.x + bt.x, 0.f);
            float yB1 = fmaxf((acc[t][3] - muB) * rsB * gg.y + bt.y, 0.f);
            *reinterpret_cast<float2*>(outA + col) = make_float2(yA0, yA1);
            *reinterpret_cast<float2*>(outB + col) = make_float2(yB0, yB1);
            float p0 = fmaxf(mA ? yA0 : 0.f, mB ? yB0 : 0.f);
            float p1 = fmaxf(mA ? yA1 : 0.f, mB ? yB1 : 0.f);
            pool0[t] = fmaxf(pool0[t], p0);
            pool1[t] = fmaxf(pool1[t], p1);
        }
    }

    // intra-warp pooled-max reduce over the 8 q-groups (lane bits 2..4)
    #pragma unroll
    for (int t = 0; t < 16; t++) {
        #pragma unroll
        for (int m = 4; m <= 16; m <<= 1) {
            pool0[t] = fmaxf(pool0[t], __shfl_xor_sync(0xffffffffu, pool0[t], m));
            pool1[t] = fmaxf(pool1[t], __shfl_xor_sync(0xffffffffu, pool1[t], m));
        }
    }
    if (q == 0) {
        #pragma unroll
        for (int t = 0; t < 16; t++) {
            sPool[warp * 128 + t * 8 + 2 * s]     = pool0[t];
            sPool[warp * 128 + t * 8 + 2 * s + 1] = pool1[t];
        }
    }
    __syncthreads();

    // cross-warp reduce -> g
    if (tid < 128) {
        float m = sPool[tid];
        #pragma unroll
        for (int w = 1; w < 8; w++) m = fmaxf(m, sPool[w * 128 + tid]);
        gsm[tid] = m;
        gout[(size_t)n * Hdim + tid] = m;
    }
    __syncthreads();

    // broadcast g into out[n, :, H:2H]
    const float4 gv = *reinterpret_cast<const float4*>(gsm + (tid & 31) * 4);
    float* obase = out + (size_t)n * L * (2 * Hdim) + Hdim;
    for (int r = tid >> 5; r < L; r += 8)
        *reinterpret_cast<float4*>(obase + (size_t)r * (2 * Hdim) + (tid & 31) * 4) = gv;
}

extern "C" void kernel_launch(void* const* d_in, const int* in_sizes, int n_in,
                              void* d_out, int out_size) {
    const float* x     = (const float*)d_in[0];
    const int*   mask  = (const int*)d_in[1];
    const float* W     = (const float*)d_in[2];
    const float* bias  = (const float*)d_in[3];
    const float* gamma = (const float*)d_in[4];
    const float* beta  = (const float*)d_in[5];
    float* out = (float*)d_out;

    const int NL = in_sizes[1];                          // N*L (mask element count)
    const long long ysize = (long long)NL * 2 * Hdim;    // out[N,L,2H] elements
    const int N = (int)(((long long)out_size - ysize) / Hdim);
    const int L = NL / N;
    float* g = out + ysize;                              // g[N,H] tail

    fused_kernel<<<N, 256>>>(x, mask, W, bias, gamma, beta, out, g, L);
}

// round 3
// speedup vs baseline: 1.4167x; 1.3235x over previous
#include <cuda_runtime.h>
#include <cuda_bf16.h>
#include <cstdint>

#define LN_EPS 1e-5f

static constexpr int Fdim = 64;
static constexpr int Hdim = 128;

__device__ __forceinline__ float bf16_round(float x) {
    return __bfloat162float(__float2bfloat16_rn(x));
}
__device__ __forceinline__ uint32_t packbf(float lo, float hi) {
    uint32_t r;
    asm("cvt.rn.bf16x2.f32 %0, %1, %2;" : "=r"(r) : "f"(hi), "f"(lo));
    return r;
}

__device__ __forceinline__ void mma_bf16(float c[4], const uint32_t a[4], const uint32_t b[2]) {
    asm volatile(
        "mma.sync.aligned.m16n8k16.row.col.f32.bf16.bf16.f32 "
        "{%0,%1,%2,%3}, {%4,%5,%6,%7}, {%8,%9}, {%0,%1,%2,%3};\n"
        : "+f"(c[0]), "+f"(c[1]), "+f"(c[2]), "+f"(c[3])
        : "r"(a[0]), "r"(a[1]), "r"(a[2]), "r"(a[3]), "r"(b[0]), "r"(b[1]));
}

// One CTA per batch n; 16 warps x 16 rows = 256 rows/sweep, L/256 sweeps.
// bf16x3-split GEMM -> bias -> LN -> ReLU -> write y; pooled max flushed to smem
// atomics each sweep (no persistent pool regs); then g write + broadcast.
extern "C" __global__ void __launch_bounds__(512, 1)
fused_kernel(const float* __restrict__ x, const int* __restrict__ mask,
             const float* __restrict__ W, const float* __restrict__ bias,
             const float* __restrict__ gamma, const float* __restrict__ beta,
             float* __restrict__ out, float* __restrict__ gout, int L)
{
    __shared__ uint4 Bfrag[4 * 16 * 32];   // 32 KB
    __shared__ int   gsm[128];             // pooled max (int-reinterpreted floats >= 0)

    const int tid = threadIdx.x;
    const int n   = blockIdx.x;

    // pack W into bf16 mma B-fragment order (hi + residual lo)
    for (int idx = tid; idx < 4 * 16 * 32; idx += 512) {
        int lane = idx & 31;
        int t    = (idx >> 5) & 15;
        int ks   = idx >> 9;
        int q = lane >> 2, s = lane & 3;
        int h  = t * 8 + q;
        int f0 = ks * 16 + s * 2;
        float2 w01 = *reinterpret_cast<const float2*>(W + h * Fdim + f0);
        float2 w89 = *reinterpret_cast<const float2*>(W + h * Fdim + f0 + 8);
        uint4 v;
        v.x = packbf(w01.x, w01.y);
        v.y = packbf(w89.x, w89.y);
        v.z = packbf(w01.x - bf16_round(w01.x), w01.y - bf16_round(w01.y));
        v.w = packbf(w89.x - bf16_round(w89.x), w89.y - bf16_round(w89.y));
        Bfrag[idx] = v;
    }
    if (tid < 128) gsm[tid] = 0;
    __syncthreads();

    const int lane = tid & 31;
    const int warp = tid >> 5;
    const int q = lane >> 2, s = lane & 3;

    for (int rb = warp * 16; rb < L; rb += 256) {
        const size_t rowA = (size_t)n * L + rb + q;
        const size_t rowB = rowA + 8;
        const float* xA = x + rowA * Fdim;
        const float* xB = x + rowB * Fdim;

        float acc[16][4];
        #pragma unroll
        for (int t = 0; t < 16; t++)
            acc[t][0] = acc[t][1] = acc[t][2] = acc[t][3] = 0.f;

        #pragma unroll
        for (int ks = 0; ks < 4; ks++) {
            const int f0 = ks * 16 + s * 2;
            float2 A0 = *reinterpret_cast<const float2*>(xA + f0);
            float2 A8 = *reinterpret_cast<const float2*>(xA + f0 + 8);
            float2 B0 = *reinterpret_cast<const float2*>(xB + f0);
            float2 B8 = *reinterpret_cast<const float2*>(xB + f0 + 8);
            uint32_t ah[4] = { packbf(A0.x, A0.y), packbf(B0.x, B0.y),
                               packbf(A8.x, A8.y), packbf(B8.x, B8.y) };
            uint32_t al[4] = {
                packbf(A0.x - bf16_round(A0.x), A0.y - bf16_round(A0.y)),
                packbf(B0.x - bf16_round(B0.x), B0.y - bf16_round(B0.y)),
                packbf(A8.x - bf16_round(A8.x), A8.y - bf16_round(A8.y)),
                packbf(B8.x - bf16_round(B8.x), B8.y - bf16_round(B8.y)) };
            const uint4* Bp = Bfrag + ks * 512 + lane;
            #pragma unroll
            for (int t = 0; t < 16; t++) {
                uint4 bv = Bp[t * 32];
                uint32_t bh[2] = { bv.x, bv.y };
                uint32_t bl[2] = { bv.z, bv.w };
                mma_bf16(acc[t], ah, bh);
                mma_bf16(acc[t], al, bh);
                mma_bf16(acc[t], ah, bl);
            }
        }

        #pragma unroll
        for (int t = 0; t < 16; t++) {
            float2 bb = *reinterpret_cast<const float2*>(bias + t * 8 + 2 * s);
            acc[t][0] += bb.x; acc[t][1] += bb.y;
            acc[t][2] += bb.x; acc[t][3] += bb.y;
        }

        float sumA = 0.f, sqA = 0.f, sumB = 0.f, sqB = 0.f;
        #pragma unroll
        for (int t = 0; t < 16; t++) {
            sumA += acc[t][0] + acc[t][1];
            sqA  += acc[t][0] * acc[t][0] + acc[t][1] * acc[t][1];
            sumB += acc[t][2] + acc[t][3];
            sqB  += acc[t][2] * acc[t][2] + acc[t][3] * acc[t][3];
        }
        #pragma unroll
        for (int m = 1; m <= 2; m <<= 1) {
            sumA += __shfl_xor_sync(0xffffffffu, sumA, m);
            sqA  += __shfl_xor_sync(0xffffffffu, sqA, m);
            sumB += __shfl_xor_sync(0xffffffffu, sumB, m);
            sqB  += __shfl_xor_sync(0xffffffffu, sqB, m);
        }
        const float inv = 1.0f / (float)Hdim;
        float muA = sumA * inv, muB = sumB * inv;
        float rsA = rsqrtf(fmaxf(sqA * inv - muA * muA, 0.f) + LN_EPS);
        float rsB = rsqrtf(fmaxf(sqB * inv - muB * muB, 0.f) + LN_EPS);

        const bool mA = (mask[rowA] != 0);
        const bool mB = (mask[rowB] != 0);
        float* outA = out + rowA * (2 * Hdim);
        float* outB = out + rowB * (2 * Hdim);

        float p0[16], p1[16];
        #pragma unroll
        for (int t = 0; t < 16; t++) {
            int col = t * 8 + 2 * s;
            float2 gg = *reinterpret_cast<const float2*>(gamma + col);
            float2 bt = *reinterpret_cast<const float2*>(beta + col);
            float yA0 = fmaxf((acc[t][0] - muA) * rsA * gg.x + bt.x, 0.f);
            float yA1 = fmaxf((acc[t][1] - muA) * rsA * gg.y + bt.y, 0.f);
            float yB0 = fmaxf((acc[t][2] - muB) * rsB * gg.x + bt.x, 0.f);
            float yB1 = fmaxf((acc[t][3] - muB) * rsB * gg.y + bt.y, 0.f);
            *reinterpret_cast<float2*>(outA + col) = make_float2(yA0, yA1);
            *reinterpret_cast<float2*>(outB + col) = make_float2(yB0, yB1);
            p0[t] = fmaxf(mA ? yA0 : 0.f, mB ? yB0 : 0.f);
            p1[t] = fmaxf(mA ? yA1 : 0.f, mB ? yB1 : 0.f);
        }

        // quad-group reduce then flush pooled max to smem (loop-local, frees regs)
        #pragma unroll
        for (int t = 0; t < 16; t++) {
            #pragma unroll
            for (int m = 4; m <= 16; m <<= 1) {
                p0[t] = fmaxf(p0[t], __shfl_xor_sync(0xffffffffu, p0[t], m));
                p1[t] = fmaxf(p1[t], __shfl_xor_sync(0xffffffffu, p1[t], m));
            }
        }
        if (q == 0) {
            #pragma unroll
            for (int t = 0; t < 16; t++) {
                atomicMax(&gsm[t * 8 + 2 * s],     __float_as_int(p0[t]));
                atomicMax(&gsm[t * 8 + 2 * s + 1], __float_as_int(p1[t]));
            }
        }
    }
    __syncthreads();

    if (tid < 128)
        gout[(size_t)n * Hdim + tid] = __int_as_float(gsm[tid]);

    // broadcast g into out[n, :, H:2H] — 16 warps x float4 lanes
    const int h4 = lane & 31;
    float4 gv;
    gv.x = __int_as_float(gsm[h4 * 4 + 0]);
    gv.y = __int_as_float(gsm[h4 * 4 + 1]);
    gv.z = __int_as_float(gsm[h4 * 4 + 2]);
    gv.w = __int_as_float(gsm[h4 * 4 + 3]);
    float* obase = out + (size_t)n * L * (2 * Hdim) + Hdim;
    for (int r = warp; r < L; r += 16)
        *reinterpret_cast<float4*>(obase + (size_t)r * (2 * Hdim) + h4 * 4) = gv;
}

extern "C" void kernel_launch(void* const* d_in, const int* in_sizes, int n_in,
                              void* d_out, int out_size) {
    const float* x     = (const float*)d_in[0];
    const int*   mask  = (const int*)d_in[1];
    const float* W     = (const float*)d_in[2];
    const float* bias  = (const float*)d_in[3];
    const float* gamma = (const float*)d_in[4];
    const float* beta  = (const float*)d_in[5];
    float* out = (float*)d_out;

    const int NL = in_sizes[1];
    const long long ysize = (long long)NL * 2 * Hdim;
    const int N = (int)(((long long)out_size - ysize) / Hdim);
    const int L = NL / N;
    float* g = out + ysize;

    fused_kernel<<<N, 512>>>(x, mask, W, bias, gamma, beta, out, g, L);
}